// round 5
// baseline (speedup 1.0000x reference)
#include <cuda_runtime.h>
#include <cstdint>
#include <cstddef>

// ---------------------------------------------------------------------------
// Persistent tf32 mma.sync LSTM rollout.
//   B=4096 rows, H=128, D_IO=80, K=208 (=[x|h]), 4H=512 gates, T=512 steps.
//   128 CTAs x 256 threads; CTA owns 32 batch rows for the whole rollout.
//   Weights pre-packed (tf32, fragment-ordered) by a prepass kernel into
//   __device__ globals. 200KB of them (3/8 of gate weights + all of W_fc)
//   are pinned in dynamic smem once per launch; the remaining 5/8 of gate
//   weights stream from L2 via coalesced LDG.128, software-pipelined 1 deep
//   so the ~234-262cyc L2 latency hides under the current iteration's MMAs.
//   z (=[x|h], tf32) lives in static smem pre-swizzled to A-fragment layout.
//   Warp w owns gate columns [16w,16w+16) of ALL FOUR gates i/f/g/o, so the
//   LSTM pointwise update runs on accumulator registers; c stays in regs.
// ---------------------------------------------------------------------------

#define HDIM    128
#define DIO     80
#define KDIM    208
#define NGATE   512
#define BTILE   32
#define NWARPS  8
#define NTHREADS 256
#define NKT     26      // KDIM/8 k-tiles
#define NKTP    13      // k-tile pairs
#define YNT     10      // DIO/8 n-tiles for the fc GEMM
#define YNKTP   8       // HDIM/16 k-tile pairs for the fc GEMM

#define NTA_F4    (NKTP * 32)            // 416 float4 per gate n-tile
#define NTA_FL    (NTA_F4 * 4)           // 1664 floats per gate n-tile
#define WG_ELEMS  (64 * NTA_FL)          // 106496 floats (512x208 packed)
#define WFC_ELEMS (YNT * YNKTP * 32 * 4) // 10240 floats  (80x128 packed)

#define NCACHED_GRP 3                          // (gate,e) groups pinned in smem
#define NSTREAM     (8 - NCACHED_GRP)          // 5 L2-streamed groups per warp
#define CACHE_G_FL  (NCACHED_GRP * 8 * NTA_FL) // 39936 floats
#define DYN_FLOATS  (CACHE_G_FL + WFC_ELEMS)   // 50176 floats
#define DYN_BYTES   (DYN_FLOATS * 4)           // 200704 bytes

__device__ float g_Wg[WG_ELEMS];
__device__ float g_Wfc[WFC_ELEMS];
__device__ float g_bias[NGATE];
__device__ float g_biasfc[DIO];

// ---------------- helpers ----------------

__device__ __forceinline__ float tf32r(float x) {
    unsigned u;
    asm("cvt.rna.tf32.f32 %0, %1;" : "=r"(u) : "f"(x));
    return __uint_as_float(u);
}

__device__ __forceinline__ void mma_tf32(float4& d, const float4& a, float b0, float b1) {
    asm volatile(
        "mma.sync.aligned.m16n8k8.row.col.f32.tf32.tf32.f32 "
        "{%0,%1,%2,%3}, {%4,%5,%6,%7}, {%8,%9}, {%0,%1,%2,%3};"
        : "+f"(d.x), "+f"(d.y), "+f"(d.z), "+f"(d.w)
        : "r"(__float_as_uint(a.x)), "r"(__float_as_uint(a.y)),
          "r"(__float_as_uint(a.z)), "r"(__float_as_uint(a.w)),
          "r"(__float_as_uint(b0)), "r"(__float_as_uint(b1)));
}

// fast sigmoid/tanh: ex2.approx + rcp.approx (rel err ~2^-21, far inside the
// tf32 error budget); saturates correctly at +/-inf.
__device__ __forceinline__ float fex2(float x) {
    float y; asm("ex2.approx.f32 %0, %1;" : "=f"(y) : "f"(x)); return y;
}
__device__ __forceinline__ float frcp(float x) {
    float y; asm("rcp.approx.f32 %0, %1;" : "=f"(y) : "f"(x)); return y;
}
__device__ __forceinline__ float sigf(float x) {
    return frcp(1.0f + fex2(-1.4426950408889634f * x));
}
__device__ __forceinline__ float tanhp(float x) {
    return 1.0f - 2.0f * frcp(fex2(2.8853900817779268f * x) + 1.0f);
}

__device__ __forceinline__ float eltone(float gi, float gf, float gg, float go, float& c) {
    float iv = sigf(gi), fv = sigf(gf), gv = tanhp(gg), ov = sigf(go);
    c = fv * c + iv * gv;
    return ov * tanhp(c);
}

// smem z layout: zs[mt][kt][lane][4] so one LDS.128 = one A fragment.
__device__ __forceinline__ int zoff(int mt, int kt, int lane) {
    return ((mt * NKT + kt) * 32 + lane) * 4;
}
// scatter address for logical z element (row b in 0..31, col k in 0..207)
__device__ __forceinline__ int zidx(int b, int k) {
    int mt = b >> 4, r = b & 15, gg = r & 7, rh = r >> 3;
    int kt = k >> 3, kk = k & 7, tg = kk & 3, kh = kk >> 2;
    return zoff(mt, kt, gg * 4 + tg) + rh + 2 * kh;
}

// ---------------- prepass: pack weights into fragment order (tf32) ----------
// g_Wg float idx = ((nta*13 + ktp)*32 + lane)*4 + q
//   q=0: b0 of kt=2ktp   q=1: b1 of kt=2ktp   q=2: b0 of kt=2ktp+1   q=3: b1
// with n = nta*8 + (lane>>2), fragment row offset tig = lane&3.
// b0 covers W[n][k0+tig], b1 covers W[n][k0+tig+4]. Same scheme for g_Wfc.

__global__ void prep_kernel(const float* __restrict__ W_ih,
                            const float* __restrict__ W_hh,
                            const float* __restrict__ b_ih,
                            const float* __restrict__ b_hh,
                            const float* __restrict__ W_fc,
                            const float* __restrict__ b_fc) {
    int idx = blockIdx.x * blockDim.x + threadIdx.x;
    if (idx < WG_ELEMS) {
        int q = idx & 3, lane = (idx >> 2) & 31, r = idx >> 7;
        int ktp = r % NKTP, nt = r / NKTP;
        int gg = lane >> 2, tig = lane & 3;
        int n = nt * 8 + gg;
        int k = (2 * ktp + (q >> 1)) * 8 + tig + ((q & 1) << 2);
        float v = (k < DIO) ? W_ih[n * DIO + k] : W_hh[n * HDIM + (k - DIO)];
        g_Wg[idx] = tf32r(v);
    } else if (idx < WG_ELEMS + WFC_ELEMS) {
        int i2 = idx - WG_ELEMS;
        int q = i2 & 3, lane = (i2 >> 2) & 31, r = i2 >> 7;
        int p = r % YNKTP, nt = r / YNKTP;
        int gg = lane >> 2, tig = lane & 3;
        int n = nt * 8 + gg;                                     // n < 80
        int k = (2 * p + (q >> 1)) * 8 + tig + ((q & 1) << 2);   // k < 128
        g_Wfc[i2] = tf32r(W_fc[n * HDIM + k]);
    } else if (idx < WG_ELEMS + WFC_ELEMS + NGATE) {
        int i3 = idx - WG_ELEMS - WFC_ELEMS;
        g_bias[i3] = b_ih[i3] + b_hh[i3];
    } else if (idx < WG_ELEMS + WFC_ELEMS + NGATE + DIO) {
        int i4 = idx - WG_ELEMS - WFC_ELEMS - NGATE;
        g_biasfc[i4] = b_fc[i4];
    }
}

// ---------------- main persistent kernel ----------------

__global__ __launch_bounds__(NTHREADS, 1)
void lstm_kernel(const float* __restrict__ hn, float* __restrict__ out,
                 const int* __restrict__ seqp) {
    extern __shared__ float wcache[];        // [CACHE_G_FL gate wts | WFC copy]
    __shared__ float zs[2 * NKT * 32 * 4];   // 6656 floats: z=[x|h], frag layout
    __shared__ float bias_s[NGATE];
    __shared__ float biasfc_s[DIO];

    const int tid  = threadIdx.x;
    const int w    = tid >> 5;
    const int lane = tid & 31;
    const int gg   = lane >> 2;     // groupID
    const int tig  = lane & 3;      // thread-in-group
    const int bbase = blockIdx.x * BTILE;
    const int T = seqp ? *seqp : 512;

    for (int i = tid; i < NGATE; i += NTHREADS) bias_s[i] = g_bias[i];
    for (int i = tid; i < DIO;   i += NTHREADS) biasfc_s[i] = g_biasfc[i];
    for (int i = tid; i < 2 * NKT * 32 * 4; i += NTHREADS) zs[i] = 0.0f; // x0=0

    // pin 3 (gate,e)-groups of gate weights in smem: group g holds ntas
    //   { (g>>1)*16 + 2*w' + (g&1) : w'=0..7 }  at wcache[(g*8+w')*NTA_FL ..]
    // so every warp has exactly 3 of its 8 weight streams in smem (balanced).
    for (int i = tid; i < CACHE_G_FL; i += NTHREADS) {
        int j = i % NTA_FL;
        int s = i / NTA_FL;          // s = g*8 + w'
        int g = s >> 3, wp = s & 7;
        int nta = ((g >> 1) << 4) + 2 * wp + (g & 1);
        wcache[i] = g_Wg[nta * NTA_FL + j];
    }
    for (int i = tid; i < WFC_ELEMS; i += NTHREADS)
        wcache[CACHE_G_FL + i] = g_Wfc[i];
    __syncthreads();

    // h0 = quantized_hn
    for (int i = tid; i < BTILE * HDIM; i += NTHREADS) {
        int b = i >> 7, j = i & 127;
        zs[zidx(b, DIO + j)] = tf32r(hn[(bbase + b) * HDIM + j]);
    }
    __syncthreads();

    // c state in registers: creg[e][mt] matches acc fragment positions
    float4 creg[2][2];
#pragma unroll
    for (int e = 0; e < 2; ++e)
#pragma unroll
        for (int mt = 0; mt < 2; ++mt)
            creg[e][mt] = make_float4(0.f, 0.f, 0.f, 0.f);

    const float4* __restrict__ wg4  = reinterpret_cast<const float4*>(g_Wg);
    const float4* __restrict__ wf4s = reinterpret_cast<const float4*>(wcache + CACHE_G_FL);
    const int w2 = 2 * w;

    // per-warp weight stream bases: ni in 0..2 -> smem-pinned, 3..7 -> gmem/L2
    const float4* wsm[NCACHED_GRP];
    const float4* wgl[NSTREAM];
#pragma unroll
    for (int ni = 0; ni < NCACHED_GRP; ++ni)
        wsm[ni] = reinterpret_cast<const float4*>(wcache) + (ni * 8 + w) * NTA_F4;
#pragma unroll
    for (int u = 0; u < NSTREAM; ++u) {
        int ni = NCACHED_GRP + u;
        int nta = ((ni >> 1) << 4) + w2 + (ni & 1);
        wgl[u] = wg4 + nta * NTA_F4;
    }

#pragma unroll 1
    for (int t = 0; t < T; ++t) {
        // ---- phase A: gates GEMM [32 x 512] = z @ W^T + bias --------------
        // warp w owns n-tiles {a*16 + 2w + e : a in 0..3 (i,f,g,o), e in 0..1}
        float4 acc[8][2];
#pragma unroll
        for (int ni = 0; ni < 8; ++ni) {
            int nta = ((ni >> 1) << 4) + w2 + (ni & 1);
            int col = nta * 8 + 2 * tig;
            float b0 = bias_s[col], b1 = bias_s[col + 1];
            acc[ni][0] = make_float4(b0, b1, b0, b1);
            acc[ni][1] = make_float4(b0, b1, b0, b1);
        }
        // 1-deep software pipeline on the 5 L2-streamed weight groups: the
        // loads for iteration ktp+1 issue before iteration ktp's MMAs, so
        // ~234-262cyc of L2 latency hides under ~32 MMAs + smem traffic.
        float4 pw[NSTREAM];
#pragma unroll
        for (int u = 0; u < NSTREAM; ++u) pw[u] = wgl[u][lane];
#pragma unroll 1
        for (int ktp = 0; ktp < NKTP; ++ktp) {
            float4 cw[NSTREAM];
#pragma unroll
            for (int u = 0; u < NSTREAM; ++u) cw[u] = pw[u];
            int nwi = (ktp + 1 < NKTP ? ktp + 1 : 0) * 32 + lane;  // wrap: harmless
#pragma unroll
            for (int u = 0; u < NSTREAM; ++u) pw[u] = wgl[u][nwi];

            float4 aA0 = *(const float4*)(zs + zoff(0, 2 * ktp,     lane));
            float4 aA1 = *(const float4*)(zs + zoff(1, 2 * ktp,     lane));
            float4 aB0 = *(const float4*)(zs + zoff(0, 2 * ktp + 1, lane));
            float4 aB1 = *(const float4*)(zs + zoff(1, 2 * ktp + 1, lane));
            int wi = ktp * 32 + lane;
#pragma unroll
            for (int ni = 0; ni < NCACHED_GRP; ++ni) {
                float4 wq = wsm[ni][wi];
                mma_tf32(acc[ni][0], aA0, wq.x, wq.y);
                mma_tf32(acc[ni][1], aA1, wq.x, wq.y);
                mma_tf32(acc[ni][0], aB0, wq.z, wq.w);
                mma_tf32(acc[ni][1], aB1, wq.z, wq.w);
            }
#pragma unroll
            for (int u = 0; u < NSTREAM; ++u) {
                int ni = NCACHED_GRP + u;
                mma_tf32(acc[ni][0], aA0, cw[u].x, cw[u].y);
                mma_tf32(acc[ni][1], aA1, cw[u].x, cw[u].y);
                mma_tf32(acc[ni][0], aB0, cw[u].z, cw[u].w);
                mma_tf32(acc[ni][1], aB1, cw[u].z, cw[u].w);
            }
        }
        __syncthreads();   // all warps done reading zs (old h) before overwrite

        // ---- phase B: LSTM pointwise, entirely in registers ---------------
#pragma unroll
        for (int e = 0; e < 2; ++e) {
#pragma unroll
            for (int mt = 0; mt < 2; ++mt) {
                float4 I = acc[0 + e][mt];
                float4 F = acc[2 + e][mt];
                float4 G = acc[4 + e][mt];
                float4 O = acc[6 + e][mt];
                float4& C = creg[e][mt];
                int j0  = (w << 4) + (e << 3) + 2 * tig;
                int blo = mt * 16 + gg;
                int bhi = blo + 8;
                float h0 = eltone(I.x, F.x, G.x, O.x, C.x);
                zs[zidx(blo, DIO + j0)]     = tf32r(h0);
                float h1 = eltone(I.y, F.y, G.y, O.y, C.y);
                zs[zidx(blo, DIO + j0 + 1)] = tf32r(h1);
                float h2 = eltone(I.z, F.z, G.z, O.z, C.z);
                zs[zidx(bhi, DIO + j0)]     = tf32r(h2);
                float h3 = eltone(I.w, F.w, G.w, O.w, C.w);
                zs[zidx(bhi, DIO + j0 + 1)] = tf32r(h3);
            }
        }
        __syncthreads();   // new h visible to all warps

        // ---- phase C: y = h @ W_fc^T + b_fc; emit + feed back as next x ----
        for (int nt = w; nt < YNT; nt += NWARPS) {
            int col0 = nt * 8 + 2 * tig;
            float bb0 = biasfc_s[col0], bb1 = biasfc_s[col0 + 1];
            float4 y0 = make_float4(bb0, bb1, bb0, bb1);
            float4 y1 = make_float4(bb0, bb1, bb0, bb1);
#pragma unroll
            for (int p = 0; p < YNKTP; ++p) {
                float4 aA0 = *(const float4*)(zs + zoff(0, 10 + 2 * p, lane));
                float4 aA1 = *(const float4*)(zs + zoff(1, 10 + 2 * p, lane));
                float4 aB0 = *(const float4*)(zs + zoff(0, 11 + 2 * p, lane));
                float4 aB1 = *(const float4*)(zs + zoff(1, 11 + 2 * p, lane));
                float4 wq = wf4s[(nt * YNKTP + p) * 32 + lane];
                mma_tf32(y0, aA0, wq.x, wq.y);
                mma_tf32(y1, aA1, wq.x, wq.y);
                mma_tf32(y0, aB0, wq.z, wq.w);
                mma_tf32(y1, aB1, wq.z, wq.w);
            }
            int rows[4] = { gg, gg + 8, 16 + gg, 24 + gg };
            float vx[4] = { y0.x, y0.z, y1.x, y1.z };
            float vy[4] = { y0.y, y0.w, y1.y, y1.w };
#pragma unroll
            for (int rr = 0; rr < 4; ++rr) {
                int bl = rows[rr];
                size_t o = ((size_t)(bbase + bl) * (size_t)T + (size_t)t) * DIO + col0;
                *reinterpret_cast<float2*>(out + o) = make_float2(vx[rr], vy[rr]);
                zs[zidx(bl, col0)]     = tf32r(vx[rr]);
                zs[zidx(bl, col0 + 1)] = tf32r(vy[rr]);
            }
        }
        __syncthreads();   // next x in place before next step's GEMM
    }
}

// ---------------- launch ----------------

extern "C" void kernel_launch(void* const* d_in, const int* in_sizes, int n_in,
                              void* d_out, int out_size) {
    const float* hn   = (const float*)d_in[0];   // (4096,128)
    const float* W_ih = (const float*)d_in[1];   // (512,80)
    const float* W_hh = (const float*)d_in[2];   // (512,128)
    const float* b_ih = (const float*)d_in[3];   // (512)
    const float* b_hh = (const float*)d_in[4];   // (512)
    const float* W_fc = (const float*)d_in[5];   // (80,128)
    const float* b_fc = (const float*)d_in[6];   // (80)
    const int*  seqp  = (n_in > 7) ? (const int*)d_in[7] : nullptr;  // seq_len
    float* out = (float*)d_out;                  // (4096, T, 80)

    // opt-in to >48KB dynamic smem; idempotent, not a stream op (safe during
    // graph capture), called unconditionally to stay deterministic.
    cudaFuncSetAttribute(lstm_kernel,
                         cudaFuncAttributeMaxDynamicSharedMemorySize,
                         DYN_BYTES);

    int prep_total = WG_ELEMS + WFC_ELEMS + NGATE + DIO;
    prep_kernel<<<(prep_total + 255) / 256, 256>>>(W_ih, W_hh, b_ih, b_hh, W_fc, b_fc);
    lstm_kernel<<<4096 / BTILE, NTHREADS, DYN_BYTES>>>(hn, out, seqp);
}

// round 10
// speedup vs baseline: 1.3932x; 1.3932x over previous
#include <cuda_runtime.h>
#include <cuda_fp16.h>
#include <cstdint>
#include <cstddef>

// ---------------------------------------------------------------------------
// Persistent fp16 m16n8k16 mma.sync LSTM rollout (fp32 accumulate).
//   B=4096 rows, H=128, D_IO=80, K=208 (=[x|h]), 4H=512 gates, T=512 steps.
//   128 CTAs x 512 threads (16 warps); CTA owns 32 batch rows (2 m16-tiles).
//   fp16 has the SAME 10-bit mantissa as tf32 (validated rel_err=1e-4) but
//   halves MMA count (k16 vs k8) and halves all L1 bytes.
//   Warp w owns gate columns [8w,8w+8) of ALL FOUR gates i/f/g/o -> LSTM
//   pointwise update entirely in fp32 accumulator registers; c stays in regs.
//   Weights fp16, fragment-packed by prepass. Gates i/f/o pinned in smem
//   (160KB); gate g streamed from L2 (19% utilized) with 1-deep prefetch.
//   z=[x|h] in smem as fp16, pre-swizzled so one LDS.128 = one A fragment.
// ---------------------------------------------------------------------------

#define HDIM     128
#define DIO      80
#define KDIM     208
#define NGATE    512
#define BTILE    32
#define NWARPS   16
#define NTHREADS 512
#define KT16     13      // K/16 k-tiles for gates GEMM
#define XKT      5       // k-tiles 0..4  = x region (80 = 5*16)
#define HKT      8       // k-tiles 5..12 = h region (128 = 8*16)
#define YNT      10      // DIO/8 n-tiles for fc GEMM
#define NGT      64      // gate n-tiles (512/8)

#define TILE_U2   (KT16 * 32)            // 416 uint2 per gate n-tile
#define WG_U2     (NGT * TILE_U2)        // 26624 uint2 (all gate weights)
#define WFC_U2    (YNT * 8 * 32)         // 2560 uint2 (fc weights)
#define SW_TILES  48                     // gates i,f,o cached in smem
#define SW_U2     (SW_TILES * TILE_U2)   // 19968 uint2 = 159744 B
#define DYN_BYTES ((SW_U2 + WFC_U2) * 8) // 180224 B dynamic smem

__device__ uint2 g_Wgh[WG_U2];    // (tile*13+kt)*32+lane ; tile = gate*16+wt
__device__ uint2 g_Wfch[WFC_U2];  // (nt*8+kt)*32+lane
__device__ float g_bias[NGATE];
__device__ float g_biasfc[DIO];

// ---------------- helpers ----------------

__device__ __forceinline__ void mma_f16(float4& d, const uint4& a, const uint2& b) {
    asm volatile(
        "mma.sync.aligned.m16n8k16.row.col.f32.f16.f16.f32 "
        "{%0,%1,%2,%3}, {%4,%5,%6,%7}, {%8,%9}, {%0,%1,%2,%3};"
        : "+f"(d.x), "+f"(d.y), "+f"(d.z), "+f"(d.w)
        : "r"(a.x), "r"(a.y), "r"(a.z), "r"(a.w), "r"(b.x), "r"(b.y));
}

__device__ __forceinline__ float fex2(float x) {
    float y; asm("ex2.approx.f32 %0, %1;" : "=f"(y) : "f"(x)); return y;
}
__device__ __forceinline__ float frcp(float x) {
    float y; asm("rcp.approx.f32 %0, %1;" : "=f"(y) : "f"(x)); return y;
}
__device__ __forceinline__ float sigf(float x) {
    return frcp(1.0f + fex2(-1.4426950408889634f * x));
}
__device__ __forceinline__ float tanhp(float x) {
    return 1.0f - 2.0f * frcp(fex2(2.8853900817779268f * x) + 1.0f);
}
__device__ __forceinline__ float eltone(float gi, float gf, float gg, float go, float& c) {
    float iv = sigf(gi), fv = sigf(gf), gv = tanhp(gg), ov = sigf(go);
    c = fv * c + iv * gv;
    return ov * tanhp(c);
}

__device__ __forceinline__ unsigned pack2(float a, float b) {
    __half2 h = __floats2half2_rn(a, b);
    return *reinterpret_cast<unsigned*>(&h);
}

// zs half-index for logical element (b in 0..31, k in 0..207).
// Layout: uint4 per (mt, kt, lane) = {a0,a1,a2,a3} of the m16n8k16 A frag:
//   a0: row gg,   cols {k0+2tg, +1}   a1: row gg+8, same cols
//   a2: row gg,   cols {k0+8+2tg,+1}  a3: row gg+8, same cols
__device__ __forceinline__ int zhidx(int b, int k) {
    int mt = b >> 4, r = b & 15, rl = r & 7, rh = r >> 3;
    int kt = k >> 4, kk = k & 15, kh = kk >> 3, tg = (kk & 7) >> 1, hf = kk & 1;
    int q = rh + 2 * kh;
    return (((mt * KT16 + kt) * 32) + rl * 4 + tg) * 8 + q * 2 + hf;
}

// ---------------- prepass: pack fp16 fragment-ordered weights ----------------
// B frag (m16n8k16, col): b0 = {B[k0+2tig][gg], B[k0+2tig+1][gg]},
//                         b1 = {B[k0+2tig+8][gg], B[k0+2tig+9][gg]}
// with B[k][n] = W[n][k];  gate tile t covers gate-vector rows [8t, 8t+8).

__global__ void prep_kernel(const float* __restrict__ W_ih,
                            const float* __restrict__ W_hh,
                            const float* __restrict__ b_ih,
                            const float* __restrict__ b_hh,
                            const float* __restrict__ W_fc,
                            const float* __restrict__ b_fc) {
    int idx = blockIdx.x * blockDim.x + threadIdx.x;
    if (idx < WG_U2) {
        int lane = idx & 31, kt = (idx >> 5) % KT16, tile = idx / TILE_U2;
        int gg = lane >> 2, tig = lane & 3;
        int n = tile * 8 + gg;
        int k0 = kt * 16 + 2 * tig;
        float v[4];
#pragma unroll
        for (int j = 0; j < 4; ++j) {
            int k = k0 + (j >> 1) * 8 + (j & 1);
            v[j] = (k < DIO) ? W_ih[n * DIO + k] : W_hh[n * HDIM + (k - DIO)];
        }
        uint2 u; u.x = pack2(v[0], v[1]); u.y = pack2(v[2], v[3]);
        g_Wgh[idx] = u;
    } else if (idx < WG_U2 + WFC_U2) {
        int i2 = idx - WG_U2;
        int lane = i2 & 31, kt = (i2 >> 5) & 7, nt = i2 / (8 * 32);
        int gg = lane >> 2, tig = lane & 3;
        int n = nt * 8 + gg;              // n < 80
        int k0 = kt * 16 + 2 * tig;       // k < 128
        float v[4];
#pragma unroll
        for (int j = 0; j < 4; ++j)
            v[j] = W_fc[n * HDIM + k0 + (j >> 1) * 8 + (j & 1)];
        uint2 u; u.x = pack2(v[0], v[1]); u.y = pack2(v[2], v[3]);
        g_Wfch[i2] = u;
    } else if (idx < WG_U2 + WFC_U2 + NGATE) {
        int i3 = idx - WG_U2 - WFC_U2;
        g_bias[i3] = b_ih[i3] + b_hh[i3];
    } else if (idx < WG_U2 + WFC_U2 + NGATE + DIO) {
        int i4 = idx - WG_U2 - WFC_U2 - NGATE;
        g_biasfc[i4] = b_fc[i4];
    }
}

// ---------------- main persistent kernel ----------------

__global__ __launch_bounds__(NTHREADS, 1)
void lstm_kernel(const float* __restrict__ hn, float* __restrict__ out,
                 const int* __restrict__ seqp) {
    extern __shared__ uint2 dsm[];                 // [SW_U2 gate wts | WFC]
    uint2* sW  = dsm;                              // slots: 0..15 i, 16..31 f, 32..47 o
    uint2* sFc = dsm + SW_U2;
    __shared__ __half zs[2 * KT16 * 32 * 8];       // 6656 halves, frag layout
    __shared__ float bias_s[NGATE];
    __shared__ float biasfc_s[DIO];

    const int tid  = threadIdx.x;
    const int w    = tid >> 5;      // 0..15
    const int lane = tid & 31;
    const int gg   = lane >> 2;
    const int tig  = lane & 3;
    const int bbase = blockIdx.x * BTILE;
    const int T = seqp ? *seqp : 512;

    for (int i = tid; i < NGATE; i += NTHREADS) bias_s[i] = g_bias[i];
    for (int i = tid; i < DIO;   i += NTHREADS) biasfc_s[i] = g_biasfc[i];
    // zero zs (x0 = 0; h region overwritten below)
    for (int i = tid; i < 2 * KT16 * 32 * 4; i += NTHREADS)
        reinterpret_cast<unsigned*>(zs)[i] = 0u;

    // cache gates i (tiles 0..15), f (16..31), o (48..63) in smem slots 0..47
    for (int i = tid; i < SW_U2; i += NTHREADS) {
        int s = i / TILE_U2;
        int srct = (s < 32) ? s : s + 16;
        sW[i] = g_Wgh[srct * TILE_U2 + (i % TILE_U2)];
    }
    for (int i = tid; i < WFC_U2; i += NTHREADS) sFc[i] = g_Wfch[i];
    __syncthreads();

    // h0 = quantized_hn (fp16 in zs h-region)
    for (int i = tid; i < BTILE * HDIM; i += NTHREADS) {
        int b = i >> 7, j = i & 127;
        zs[zhidx(b, DIO + j)] = __float2half(hn[(bbase + b) * HDIM + j]);
    }
    __syncthreads();

    // c state in fp32 registers; creg[mt] = {r gg c j0, r gg c j0+1, r gg+8 c j0, r gg+8 c j0+1}
    float4 creg[2];
    creg[0] = make_float4(0.f, 0.f, 0.f, 0.f);
    creg[1] = make_float4(0.f, 0.f, 0.f, 0.f);

    const uint4* zs4 = reinterpret_cast<const uint4*>(zs);
    const uint2* wi = sW + (0 * 16 + w) * TILE_U2;   // gate i
    const uint2* wf = sW + (1 * 16 + w) * TILE_U2;   // gate f
    const uint2* wo = sW + (2 * 16 + w) * TILE_U2;   // gate o
    const uint2* gp = g_Wgh + (32 + w) * TILE_U2;    // gate g from L2
    const int j0  = w * 8 + 2 * tig;                 // owned gate col (within H)
    const int ktb = XKT + (w >> 1);                  // h-region kt for phase B
    const int khb = w & 1;

#pragma unroll 1
    for (int t = 0; t < T; ++t) {
        // ---- phase A: gates GEMM [32 x 512] = z @ W^T + bias --------------
        float4 acc[4][2];
#pragma unroll
        for (int a = 0; a < 4; ++a) {
            int col = a * HDIM + j0;
            float b0 = bias_s[col], b1 = bias_s[col + 1];
            acc[a][0] = make_float4(b0, b1, b0, b1);
            acc[a][1] = make_float4(b0, b1, b0, b1);
        }
        uint2 pg = gp[lane];                         // prefetch g, kt=0
#pragma unroll 1
        for (int kt = 0; kt < KT16; ++kt) {
            uint2 cg = pg;
            int nk = (kt + 1 < KT16) ? kt + 1 : 0;   // wrap prefetch: harmless
            pg = gp[nk * 32 + lane];
            uint4 a0 = zs4[(0 * KT16 + kt) * 32 + lane];
            uint4 a1 = zs4[(1 * KT16 + kt) * 32 + lane];
            uint2 vi = wi[kt * 32 + lane];
            uint2 vf = wf[kt * 32 + lane];
            uint2 vo = wo[kt * 32 + lane];
            mma_f16(acc[0][0], a0, vi); mma_f16(acc[0][1], a1, vi);
            mma_f16(acc[1][0], a0, vf); mma_f16(acc[1][1], a1, vf);
            mma_f16(acc[2][0], a0, cg); mma_f16(acc[2][1], a1, cg);
            mma_f16(acc[3][0], a0, vo); mma_f16(acc[3][1], a1, vo);
        }
        __syncthreads();   // all warps done reading zs before h overwrite

        // ---- phase B: LSTM pointwise in registers; write h as fp16 --------
#pragma unroll
        for (int mt = 0; mt < 2; ++mt) {
            float4 I = acc[0][mt], F = acc[1][mt], G = acc[2][mt], O = acc[3][mt];
            float4& C = creg[mt];
            float h0 = eltone(I.x, F.x, G.x, O.x, C.x);
            float h1 = eltone(I.y, F.y, G.y, O.y, C.y);
            float h2 = eltone(I.z, F.z, G.z, O.z, C.z);
            float h3 = eltone(I.w, F.w, G.w, O.w, C.w);
            int base = ((mt * KT16 + ktb) * 32 + gg * 4 + tig) * 8;
            *reinterpret_cast<unsigned*>(zs + base + (0 + 2 * khb) * 2) = pack2(h0, h1);
            *reinterpret_cast<unsigned*>(zs + base + (1 + 2 * khb) * 2) = pack2(h2, h3);
        }
        __syncthreads();   // new h visible to all warps

        // ---- phase C: y = h @ W_fc^T + b_fc; emit fp32 + feed back fp16 ----
        for (int u = w; u < 2 * YNT; u += NWARPS) {
            int mt = u / YNT, nt = u % YNT;
            int col0 = nt * 8 + 2 * tig;
            float bb0 = biasfc_s[col0], bb1 = biasfc_s[col0 + 1];
            float4 y = make_float4(bb0, bb1, bb0, bb1);
#pragma unroll
            for (int p = 0; p < HKT; ++p) {
                uint4 a = zs4[(mt * KT16 + XKT + p) * 32 + lane];
                uint2 b = sFc[(nt * 8 + p) * 32 + lane];
                mma_f16(y, a, b);
            }
            int br0 = mt * 16 + gg, br1 = br0 + 8;
            size_t o0 = ((size_t)(bbase + br0) * (size_t)T + (size_t)t) * DIO + col0;
            size_t o1 = ((size_t)(bbase + br1) * (size_t)T + (size_t)t) * DIO + col0;
            *reinterpret_cast<float2*>(out + o0) = make_float2(y.x, y.y);
            *reinterpret_cast<float2*>(out + o1) = make_float2(y.z, y.w);
            int ktc = nt >> 1, khc = nt & 1;
            int basec = ((mt * KT16 + ktc) * 32 + gg * 4 + tig) * 8;
            *reinterpret_cast<unsigned*>(zs + basec + (0 + 2 * khc) * 2) = pack2(y.x, y.y);
            *reinterpret_cast<unsigned*>(zs + basec + (1 + 2 * khc) * 2) = pack2(y.z, y.w);
        }
        __syncthreads();   // next x in place before next step's GEMM
    }
}

// ---------------- launch ----------------

extern "C" void kernel_launch(void* const* d_in, const int* in_sizes, int n_in,
                              void* d_out, int out_size) {
    const float* hn   = (const float*)d_in[0];   // (4096,128)
    const float* W_ih = (const float*)d_in[1];   // (512,80)
    const float* W_hh = (const float*)d_in[2];   // (512,128)
    const float* b_ih = (const float*)d_in[3];   // (512)
    const float* b_hh = (const float*)d_in[4];   // (512)
    const float* W_fc = (const float*)d_in[5];   // (80,128)
    const float* b_fc = (const float*)d_in[6];   // (80)
    const int*  seqp  = (n_in > 7) ? (const int*)d_in[7] : nullptr;  // seq_len
    float* out = (float*)d_out;                  // (4096, T, 80)

    cudaFuncSetAttribute(lstm_kernel,
                         cudaFuncAttributeMaxDynamicSharedMemorySize,
                         DYN_BYTES);

    int prep_total = WG_U2 + WFC_U2 + NGATE + DIO;
    prep_kernel<<<(prep_total + 255) / 256, 256>>>(W_ih, W_hh, b_ih, b_hh, W_fc, b_fc);
    lstm_kernel<<<4096 / BTILE, NTHREADS, DYN_BYTES>>>(hn, out, seqp);
}

// round 13
// speedup vs baseline: 2.0466x; 1.4689x over previous
#include <cuda_runtime.h>
#include <cuda_fp16.h>
#include <cstdint>
#include <cstddef>

// ---------------------------------------------------------------------------
// Persistent fp16 m16n8k16 LSTM rollout with FUSED feedback GEMM.
//   Key algebra: x_t = h_t@W_fc^T + b_fc uses the SAME h_t as the recurrence,
//   so for t>=1: gates_t = h_t @ W_eff^T + b_eff, where
//     W_eff = W_hh + W_ih@W_fc   (512x128, fp32 prepass, fp16 packed)
//     b_eff = b_ih + b_hh + W_ih@b_fc
//   K drops 208->128, x never materialized, ALL weights fit in 151KB smem,
//   2 barriers/step. Step 0 (x0=0) uses W_hh/b0 straight from global (once).
//   128 CTAs x 512 threads; warp w owns gate cols [8w,8w+8) of all 4 gates;
//   LSTM pointwise in fp32 accumulator registers; c stays in registers.
// ---------------------------------------------------------------------------

#define HDIM     128
#define DIO      80
#define NGATE    512
#define BTILE    32
#define NWARPS   16
#define NTHREADS 512
#define HKT      8       // K=128 -> 8 k16-tiles
#define YNT      10      // DIO/8 n-tiles for fc GEMM

#define TILE_U2   (HKT * 32)             // 256 uint2 per gate n-tile
#define WE_U2     (64 * TILE_U2)         // 16384 uint2 (W_eff packed)
#define WFC_U2    (YNT * 8 * 32)         // 2560 uint2 (fc packed)
#define DYN_BYTES ((WE_U2 + WFC_U2) * 8) // 151552 B dynamic smem

__device__ uint2 g_Weff[WE_U2];   // (tile*8+kt)*32+lane ; tile = gate*16+w
__device__ uint2 g_W0[WE_U2];     // W_hh only (step 0), same layout
__device__ uint2 g_Wfch[WFC_U2];  // (nt*8+kt)*32+lane
__device__ float g_beff[NGATE];
__device__ float g_b0[NGATE];
__device__ float g_biasfc[DIO];

// ---------------- helpers ----------------

__device__ __forceinline__ void mma_f16(float4& d, const uint4& a, const uint2& b) {
    asm volatile(
        "mma.sync.aligned.m16n8k16.row.col.f32.f16.f16.f32 "
        "{%0,%1,%2,%3}, {%4,%5,%6,%7}, {%8,%9}, {%0,%1,%2,%3};"
        : "+f"(d.x), "+f"(d.y), "+f"(d.z), "+f"(d.w)
        : "r"(a.x), "r"(a.y), "r"(a.z), "r"(a.w), "r"(b.x), "r"(b.y));
}

__device__ __forceinline__ float fex2(float x) {
    float y; asm("ex2.approx.f32 %0, %1;" : "=f"(y) : "f"(x)); return y;
}
__device__ __forceinline__ float frcp(float x) {
    float y; asm("rcp.approx.f32 %0, %1;" : "=f"(y) : "f"(x)); return y;
}
__device__ __forceinline__ float sigf(float x) {
    return frcp(1.0f + fex2(-1.4426950408889634f * x));
}
__device__ __forceinline__ float tanhp(float x) {
    return 1.0f - 2.0f * frcp(fex2(2.8853900817779268f * x) + 1.0f);
}
__device__ __forceinline__ float eltone(float gi, float gf, float gg, float go, float& c) {
    float iv = sigf(gi), fv = sigf(gf), gv = tanhp(gg), ov = sigf(go);
    c = fv * c + iv * gv;
    return ov * tanhp(c);
}
__device__ __forceinline__ unsigned pack2(float a, float b) {
    __half2 h = __floats2half2_rn(a, b);
    return *reinterpret_cast<unsigned*>(&h);
}

// zs half-index for h element (b in 0..31, k in 0..127); uint4 per (mt,kt,lane)
// = m16n8k16 A frag {a0..a3}: a0 r=gg k-lo, a1 r=gg+8 k-lo, a2/a3 = k-hi.
__device__ __forceinline__ int zhidx(int b, int k) {
    int mt = b >> 4, r = b & 15, rl = r & 7, rh = r >> 3;
    int kt = k >> 4, kk = k & 15, kh = kk >> 3, tg = (kk & 7) >> 1, hf = kk & 1;
    int q = rh + 2 * kh;
    return (((mt * HKT + kt) * 32) + rl * 4 + tg) * 8 + q * 2 + hf;
}

// ---------------- prepass: fuse + pack (fp32 math, fp16 storage) ------------
// B frag: b0 = {W[n][k0+2tig], +1}, b1 = {+8, +9}; n = tile*8+gg.

__global__ void prep_kernel(const float* __restrict__ W_ih,
                            const float* __restrict__ W_hh,
                            const float* __restrict__ b_ih,
                            const float* __restrict__ b_hh,
                            const float* __restrict__ W_fc,
                            const float* __restrict__ b_fc) {
    int idx = blockIdx.x * blockDim.x + threadIdx.x;
    if (idx < 2 * WE_U2) {
        int eff = (idx < WE_U2) ? 1 : 0;
        int i0 = eff ? idx : idx - WE_U2;
        int lane = i0 & 31, kt = (i0 >> 5) & 7, tile = i0 >> 8;
        int gg = lane >> 2, tig = lane & 3;
        int n = tile * 8 + gg;
        int k0 = kt * 16 + 2 * tig;
        float v[4];
#pragma unroll
        for (int j = 0; j < 4; ++j) {
            int k = k0 + (j >> 1) * 8 + (j & 1);
            float s = W_hh[n * HDIM + k];
            if (eff) {
                // += W_ih[n,:] dot W_fc[:,k]
                float acc = 0.0f;
                for (int d = 0; d < DIO; ++d)
                    acc += W_ih[n * DIO + d] * W_fc[d * HDIM + k];
                s += acc;
            }
            v[j] = s;
        }
        uint2 u; u.x = pack2(v[0], v[1]); u.y = pack2(v[2], v[3]);
        if (eff) g_Weff[i0] = u; else g_W0[i0] = u;
    } else if (idx < 2 * WE_U2 + WFC_U2) {
        int i2 = idx - 2 * WE_U2;
        int lane = i2 & 31, kt = (i2 >> 5) & 7, nt = i2 / (8 * 32);
        int gg = lane >> 2, tig = lane & 3;
        int n = nt * 8 + gg;              // n < 80
        int k0 = kt * 16 + 2 * tig;       // k < 128
        float v[4];
#pragma unroll
        for (int j = 0; j < 4; ++j)
            v[j] = W_fc[n * HDIM + k0 + (j >> 1) * 8 + (j & 1)];
        uint2 u; u.x = pack2(v[0], v[1]); u.y = pack2(v[2], v[3]);
        g_Wfch[i2] = u;
    } else if (idx < 2 * WE_U2 + WFC_U2 + NGATE) {
        int n = idx - 2 * WE_U2 - WFC_U2;
        float base = b_ih[n] + b_hh[n];
        g_b0[n] = base;
        float acc = 0.0f;
        for (int d = 0; d < DIO; ++d)
            acc += W_ih[n * DIO + d] * b_fc[d];
        g_beff[n] = base + acc;
    } else if (idx < 2 * WE_U2 + WFC_U2 + NGATE + DIO) {
        int n = idx - 2 * WE_U2 - WFC_U2 - NGATE;
        g_biasfc[n] = b_fc[n];
    }
}

// ---------------- main persistent kernel ----------------

#define GATES_KT(WPTR, KT)                                                   \
    {                                                                        \
        uint4 a0 = zs4[(KT) * 32 + lane];                                    \
        uint4 a1 = zs4[(HKT + (KT)) * 32 + lane];                            \
        uint2 v0 = (WPTR)[(0 * 16 + w) * TILE_U2 + (KT) * 32 + lane];        \
        uint2 v1 = (WPTR)[(1 * 16 + w) * TILE_U2 + (KT) * 32 + lane];        \
        uint2 v2 = (WPTR)[(2 * 16 + w) * TILE_U2 + (KT) * 32 + lane];        \
        uint2 v3 = (WPTR)[(3 * 16 + w) * TILE_U2 + (KT) * 32 + lane];        \
        mma_f16(acc[0][0], a0, v0); mma_f16(acc[0][1], a1, v0);              \
        mma_f16(acc[1][0], a0, v1); mma_f16(acc[1][1], a1, v1);              \
        mma_f16(acc[2][0], a0, v2); mma_f16(acc[2][1], a1, v2);              \
        mma_f16(acc[3][0], a0, v3); mma_f16(acc[3][1], a1, v3);              \
    }

__global__ __launch_bounds__(NTHREADS, 1)
void lstm_kernel(const float* __restrict__ hn, float* __restrict__ out,
                 const int* __restrict__ seqp) {
    extern __shared__ uint2 dsm[];            // [W_eff packed | W_fc packed]
    uint2* sW  = dsm;
    uint2* sFc = dsm + WE_U2;
    __shared__ __half zs[2 * HKT * 32 * 8];   // 4096 halves: h, frag layout
    __shared__ float beff_s[NGATE];
    __shared__ float b0_s[NGATE];
    __shared__ float biasfc_s[DIO];

    const int tid  = threadIdx.x;
    const int w    = tid >> 5;      // 0..15
    const int lane = tid & 31;
    const int gg   = lane >> 2;
    const int tig  = lane & 3;
    const int bbase = blockIdx.x * BTILE;
    const int T = seqp ? *seqp : 512;

    for (int i = tid; i < NGATE; i += NTHREADS) { beff_s[i] = g_beff[i]; b0_s[i] = g_b0[i]; }
    for (int i = tid; i < DIO;   i += NTHREADS) biasfc_s[i] = g_biasfc[i];
    for (int i = tid; i < WE_U2;  i += NTHREADS) sW[i]  = g_Weff[i];
    for (int i = tid; i < WFC_U2; i += NTHREADS) sFc[i] = g_Wfch[i];
    __syncthreads();

    // h0 = quantized_hn (fp16 in zs)
    for (int i = tid; i < BTILE * HDIM; i += NTHREADS) {
        int b = i >> 7, j = i & 127;
        zs[zhidx(b, j)] = __float2half(hn[(bbase + b) * HDIM + j]);
    }
    __syncthreads();

    float4 creg[2];
    creg[0] = make_float4(0.f, 0.f, 0.f, 0.f);
    creg[1] = make_float4(0.f, 0.f, 0.f, 0.f);

    const uint4* zs4 = reinterpret_cast<const uint4*>(zs);
    const int j0  = w * 8 + 2 * tig;   // owned gate col (within H)
    const int ktb = w >> 1;            // kt this warp's h cols land in
    const int khb = w & 1;

#pragma unroll 1
    for (int t = 0; t < T; ++t) {
        // ---- phase A: gates = h @ W^T + bias (K=128, all-smem weights) ----
        float4 acc[4][2];
        {
            const float* bp = (t == 0) ? b0_s : beff_s;
#pragma unroll
            for (int a = 0; a < 4; ++a) {
                int col = a * HDIM + j0;
                float v0 = bp[col], v1 = bp[col + 1];
                acc[a][0] = make_float4(v0, v1, v0, v1);
                acc[a][1] = make_float4(v0, v1, v0, v1);
            }
        }
        if (t == 0) {
            const uint2* wp = g_W0;     // one-time global read; x0 = 0
#pragma unroll
            for (int kt = 0; kt < HKT; ++kt) GATES_KT(wp, kt)
        } else {
#pragma unroll
            for (int kt = 0; kt < HKT; ++kt) GATES_KT(sW, kt)
        }
        __syncthreads();   // all warps done reading h before overwrite

        // ---- phase B: LSTM pointwise in registers; write h_new as fp16 ----
#pragma unroll
        for (int mt = 0; mt < 2; ++mt) {
            float4 I = acc[0][mt], F = acc[1][mt], G = acc[2][mt], O = acc[3][mt];
            float4& C = creg[mt];
            float h0 = eltone(I.x, F.x, G.x, O.x, C.x);
            float h1 = eltone(I.y, F.y, G.y, O.y, C.y);
            float h2 = eltone(I.z, F.z, G.z, O.z, C.z);
            float h3 = eltone(I.w, F.w, G.w, O.w, C.w);
            int base = ((mt * HKT + ktb) * 32 + gg * 4 + tig) * 8;
            *reinterpret_cast<unsigned*>(zs + base + (2 * khb) * 2)     = pack2(h0, h1);
            *reinterpret_cast<unsigned*>(zs + base + (1 + 2 * khb) * 2) = pack2(h2, h3);
        }
        __syncthreads();   // h_new visible to all warps

        // ---- phase C: y = h_new @ W_fc^T + b_fc -> gmem only (no feedback).
        // Next iteration's phase A also only READS zs, so no barrier between
        // C and A(t+1); the phase-A barrier protects both.
        for (int u = w; u < 2 * YNT; u += NWARPS) {
            int mt = u / YNT, nt = u % YNT;
            int col0 = nt * 8 + 2 * tig;
            float bb0 = biasfc_s[col0], bb1 = biasfc_s[col0 + 1];
            float4 ya = make_float4(bb0, bb1, bb0, bb1);
            float4 yb = make_float4(0.f, 0.f, 0.f, 0.f);
#pragma unroll
            for (int p = 0; p < 4; ++p) {
                mma_f16(ya, zs4[(mt * HKT + p) * 32 + lane],
                        sFc[(nt * 8 + p) * 32 + lane]);
                mma_f16(yb, zs4[(mt * HKT + 4 + p) * 32 + lane],
                        sFc[(nt * 8 + 4 + p) * 32 + lane]);
            }
            float4 y = make_float4(ya.x + yb.x, ya.y + yb.y,
                                   ya.z + yb.z, ya.w + yb.w);
            int br0 = mt * 16 + gg, br1 = br0 + 8;
            size_t o0 = ((size_t)(bbase + br0) * (size_t)T + (size_t)t) * DIO + col0;
            size_t o1 = ((size_t)(bbase + br1) * (size_t)T + (size_t)t) * DIO + col0;
            *reinterpret_cast<float2*>(out + o0) = make_float2(y.x, y.y);
            *reinterpret_cast<float2*>(out + o1) = make_float2(y.z, y.w);
        }
    }
}

// ---------------- launch ----------------

extern "C" void kernel_launch(void* const* d_in, const int* in_sizes, int n_in,
                              void* d_out, int out_size) {
    const float* hn   = (const float*)d_in[0];   // (4096,128)
    const float* W_ih = (const float*)d_in[1];   // (512,80)
    const float* W_hh = (const float*)d_in[2];   // (512,128)
    const float* b_ih = (const float*)d_in[3];   // (512)
    const float* b_hh = (const float*)d_in[4];   // (512)
    const float* W_fc = (const float*)d_in[5];   // (80,128)
    const float* b_fc = (const float*)d_in[6];   // (80)
    const int*  seqp  = (n_in > 7) ? (const int*)d_in[7] : nullptr;  // seq_len
    float* out = (float*)d_out;                  // (4096, T, 80)

    cudaFuncSetAttribute(lstm_kernel,
                         cudaFuncAttributeMaxDynamicSharedMemorySize,
                         DYN_BYTES);

    int prep_total = 2 * WE_U2 + WFC_U2 + NGATE + DIO;
    prep_kernel<<<(prep_total + 255) / 256, 256>>>(W_ih, W_hh, b_ih, b_hh, W_fc, b_fc);
    lstm_kernel<<<4096 / BTILE, NTHREADS, DYN_BYTES>>>(hn, out, seqp);
}